// round 17
// baseline (speedup 1.0000x reference)
#include <cuda_runtime.h>
#include <cuda_bf16.h>
#include <cstdint>

// Problem constants
#define BB      512      // batch
#define INU     8        // in_units (k)
#define INCH    1152     // in_channels (i)
#define NU      10       // num_units (j)
#define US      16       // unit_size (u)
#define JU      160      // NU*US
#define KI      9216     // INU*INCH
#define BETA    1.45f
#define KSPLIT  36
#define KCH     256      // fp32 K per chunk; processed in two 128-halves
#define BSPLIT  2        // gemm2 batch split
#define BCHUNK  (BB / BSPLIT)   // 256, two 128-halves

// ---- gemm1 smem (2-plane): Ahi/Alo [128][136], Bhi/Blo [160][136] bf16 -----
#define PA1       136
#define A1_PLANE  (128 * PA1 * 2)     // 34816
#define B1_PLANE  (160 * PA1 * 2)     // 43520
#define G1_AH     0
#define G1_AL     (G1_AH + A1_PLANE)
#define G1_BH     (G1_AL + A1_PLANE)  // 69632
#define G1_BL     (G1_BH + B1_PLANE)
#define SMEM_G1   (G1_BL + B1_PLANE)  // 156672

// ---- gemm2 smem: Ahi/Alo [128 b][136 ki], Bhi/Blo [128 b][168 ju] bf16 -----
#define PA2       136
#define PB2       168
#define A2_PLANE  (128 * PA2 * 2)     // 34816
#define B2_PLANE  (128 * PB2 * 2)     // 43008
#define G2_AH     0
#define G2_AL     (G2_AH + A2_PLANE)
#define G2_BH     (G2_AL + A2_PLANE)  // 69632
#define G2_BL     (G2_BH + B2_PLANE)
#define SMEM_G2   (G2_BL + B2_PLANE)  // 155648

// Scratch (device globals -- no allocation allowed)
__device__ float g_Wt[KI * JU];                 // [ki][ju]  (bupdate + transpose src)
__device__ float g_Wtt[JU * KI];                // [ju][ki]  (scaleWb src)
__device__ __nv_bfloat16 g_Wbh[JU * KI];        // c-scaled W hi plane [ju][ki]
__device__ __nv_bfloat16 g_Wbl[JU * KI];        // c-scaled W lo plane
__device__ __nv_bfloat16 g_xh[BB * KI];         // x hi plane [b][ki]
__device__ __nv_bfloat16 g_xl[BB * KI];         // x lo plane
__device__ __nv_bfloat16 g_vh[BB * JU];         // v hi plane [b][ju]
__device__ __nv_bfloat16 g_vl[BB * JU];         // v lo plane
__device__ float g_Gpart[BSPLIT][KI * JU];
__device__ float g_spart[KSPLIT * BB * JU];     // [chunk][b][ju]
__device__ float g_bT[NU * INCH];               // logits TRANSPOSED [j][i]
__device__ float g_c[INCH * NU];                // softmax result [i][j]

// ---- helpers ---------------------------------------------------------------
__device__ __forceinline__ uint32_t s2u(const void* p) {
    uint32_t a;
    asm("{ .reg .u64 t; cvta.to.shared.u64 t, %1; cvt.u32.u64 %0, t; }" : "=r"(a) : "l"(p));
    return a;
}
__device__ __forceinline__ void cpa16(uint32_t dst, const void* src) {
    asm volatile("cp.async.cg.shared.global [%0], [%1], 16;" :: "r"(dst), "l"(src));
}
#define CP_WAIT_ALL() asm volatile("cp.async.commit_group;\n\tcp.async.wait_group 0;" ::: "memory")
__device__ __forceinline__ void ldm_x4(uint32_t* r, uint32_t addr) {
    asm volatile("ldmatrix.sync.aligned.m8n8.x4.shared.b16 {%0,%1,%2,%3}, [%4];"
                 : "=r"(r[0]), "=r"(r[1]), "=r"(r[2]), "=r"(r[3]) : "r"(addr));
}
__device__ __forceinline__ void ldm_x4t(uint32_t* r, uint32_t addr) {
    asm volatile("ldmatrix.sync.aligned.m8n8.x4.trans.shared.b16 {%0,%1,%2,%3}, [%4];"
                 : "=r"(r[0]), "=r"(r[1]), "=r"(r[2]), "=r"(r[3]) : "r"(addr));
}
__device__ __forceinline__ void mma16816(float* d, const uint32_t* a, const uint32_t* b) {
    asm volatile("mma.sync.aligned.m16n8k16.row.col.f32.bf16.bf16.f32 "
                 "{%0,%1,%2,%3}, {%4,%5,%6,%7}, {%8,%9}, {%0,%1,%2,%3};"
                 : "+f"(d[0]), "+f"(d[1]), "+f"(d[2]), "+f"(d[3])
                 : "r"(a[0]), "r"(a[1]), "r"(a[2]), "r"(a[3]), "r"(b[0]), "r"(b[1]));
}
__device__ __forceinline__ void split_bf16(float v, __nv_bfloat16& h, __nv_bfloat16& l) {
    h = __float2bfloat16_rn(v);
    l = __float2bfloat16_rn(v - __bfloat162float(h));
}

// ---------------------------------------------------------------------------
__global__ void pad_k() {}   // launch-index padding for ncu capture alignment

// g_Wt[(k*INCH+i)*JU + ju] from W[(i*JU+ju)*INU + k]
__global__ void transposeW_k(const float* __restrict__ W) {
    int idx = blockIdx.x * blockDim.x + threadIdx.x;   // over INCH*JU
    if (idx >= INCH * JU) return;
    int i = idx / JU;
    int ju = idx - i * JU;
    float4 w0 = *reinterpret_cast<const float4*>(&W[idx * 8]);
    float4 w1 = *reinterpret_cast<const float4*>(&W[idx * 8 + 4]);
    float w[8] = {w0.x, w0.y, w0.z, w0.w, w1.x, w1.y, w1.z, w1.w};
#pragma unroll
    for (int k = 0; k < 8; k++)
        g_Wt[(k * INCH + i) * JU + ju] = w[k];
}

// tiled transpose: g_Wtt[ju][ki] = g_Wt[ki][ju]
__global__ void transposeW2_k() {
    __shared__ float tile[32][33];
    int kiT = blockIdx.x * 32;
    int juT = blockIdx.y * 32;
    int tx = threadIdx.x, ty = threadIdx.y;   // 32 x 8
#pragma unroll
    for (int r = 0; r < 32; r += 8)
        tile[ty + r][tx] = g_Wt[(kiT + ty + r) * JU + juT + tx];
    __syncthreads();
#pragma unroll
    for (int r = 0; r < 32; r += 8)
        g_Wtt[(juT + ty + r) * KI + kiT + tx] = tile[tx][ty + r];
}

// one-time: split x into bf16 hi/lo planes
__global__ void splitX_k(const float* __restrict__ x) {
    int idx = blockIdx.x * blockDim.x + threadIdx.x;   // over BB*KI/4
    if (idx >= BB * KI / 4) return;
    float4 v = *reinterpret_cast<const float4*>(&x[idx * 4]);
    __nv_bfloat16 h[4], l[4];
    split_bf16(v.x, h[0], l[0]);
    split_bf16(v.y, h[1], l[1]);
    split_bf16(v.z, h[2], l[2]);
    split_bf16(v.w, h[3], l[3]);
    *reinterpret_cast<uint2*>(&g_xh[idx * 4]) = *reinterpret_cast<uint2*>(h);
    *reinterpret_cast<uint2*>(&g_xl[idx * 4]) = *reinterpret_cast<uint2*>(l);
}

// softmax over i for each j, reading TRANSPOSED logits (coalesced)
__global__ void softmax_k() {
    const int j = blockIdx.x;
    const int t = threadIdx.x;
    const int w = t >> 5;
    const int lane = t & 31;
    __shared__ float red[4];

    float v[9];
#pragma unroll
    for (int p = 0; p < 9; p++) v[p] = g_bT[j * INCH + t + p * 128];

    float mx = v[0];
#pragma unroll
    for (int p = 1; p < 9; p++) mx = fmaxf(mx, v[p]);
#pragma unroll
    for (int o = 16; o > 0; o >>= 1) mx = fmaxf(mx, __shfl_xor_sync(0xffffffffu, mx, o));
    if (lane == 0) red[w] = mx;
    __syncthreads();
    mx = fmaxf(fmaxf(red[0], red[1]), fmaxf(red[2], red[3]));

    float e[9];
    float sum = 0.0f;
#pragma unroll
    for (int p = 0; p < 9; p++) {
        e[p] = __expf(v[p] - mx);
        sum += e[p];
    }
#pragma unroll
    for (int o = 16; o > 0; o >>= 1) sum += __shfl_xor_sync(0xffffffffu, sum, o);
    __syncthreads();
    if (lane == 0) red[w] = sum;
    __syncthreads();
    float inv = 1.0f / (red[0] + red[1] + red[2] + red[3]);
#pragma unroll
    for (int p = 0; p < 9; p++) g_c[(t + p * 128) * NU + j] = e[p] * inv;
}

// per-iteration: bf16 hi/lo planes of c ⊙ Wtt  ([ju][ki] layout)
__global__ void scaleWb_k(int uniform) {
    int idx = blockIdx.x * blockDim.x + threadIdx.x;   // over JU*KI/4
    if (idx >= JU * KI / 4) return;
    int lin = idx * 4;
    int ju = lin / KI;
    int ki = lin - ju * KI;
    int j = ju >> 4;
    float4 w = *reinterpret_cast<const float4*>(&g_Wtt[lin]);
    float p[4];
    if (uniform) {
        const float cu = 1.0f / (float)INCH;
        p[0] = w.x * cu; p[1] = w.y * cu; p[2] = w.z * cu; p[3] = w.w * cu;
    } else {
        int i = ki % INCH;
        const float* cp = &g_c[i * NU + j];
        p[0] = w.x * cp[0];
        p[1] = w.y * cp[NU];
        p[2] = w.z * cp[2 * NU];
        p[3] = w.w * cp[3 * NU];
    }
    __nv_bfloat16 h[4], l[4];
#pragma unroll
    for (int q = 0; q < 4; q++) split_bf16(p[q], h[q], l[q]);
    *reinterpret_cast<uint2*>(&g_Wbh[lin]) = *reinterpret_cast<uint2*>(h);
    *reinterpret_cast<uint2*>(&g_Wbl[lin]) = *reinterpret_cast<uint2*>(l);
}

// ===========================================================================
// GEMM1 (warp mma.sync bf16, 3-product split, cp.async pure-copy prologue):
// spart[ky][b][ju] = x[m0..+128, 256-chunk] @ (c ⊙ W)[chunk, 160]
__global__ __launch_bounds__(256, 1) void gemm1mma_k() {
    extern __shared__ char smem[];
    __nv_bfloat16* AH = reinterpret_cast<__nv_bfloat16*>(smem + G1_AH);
    __nv_bfloat16* AL = reinterpret_cast<__nv_bfloat16*>(smem + G1_AL);
    __nv_bfloat16* BH = reinterpret_cast<__nv_bfloat16*>(smem + G1_BH);
    __nv_bfloat16* BL = reinterpret_cast<__nv_bfloat16*>(smem + G1_BL);
    const int tid = threadIdx.x;
    const int m0 = blockIdx.x * 128;
    const int ky = blockIdx.y;

    const int lane = tid & 31;
    const int wid = tid >> 5;
    const int m_off = (wid & 3) * 32;
    const int n_off = (wid >> 2) * 80;

    const uint32_t aOff = ((m_off + (lane & 15)) * PA1 + (lane >> 4) * 8) * 2;
    const uint32_t bOff = ((n_off + (lane & 7) + ((lane >> 4) << 3)) * PA1
                           + ((lane >> 3) & 1) * 8) * 2;
    uint32_t aPl[3] = {s2u(AH) + aOff, s2u(AH) + aOff, s2u(AL) + aOff};
    uint32_t bPl[3] = {s2u(BH) + bOff, s2u(BL) + bOff, s2u(BH) + bOff};

    const uint32_t sAH = s2u(AH), sAL = s2u(AL), sBH = s2u(BH), sBL = s2u(BL);

    float acc[2][10][4];
#pragma unroll
    for (int mf = 0; mf < 2; mf++)
#pragma unroll
        for (int nf = 0; nf < 10; nf++)
#pragma unroll
            for (int q = 0; q < 4; q++) acc[mf][nf][q] = 0.0f;

#pragma unroll
    for (int half = 0; half < 2; half++) {
        const int kb = ky * KCH + half * 128;
        if (half) __syncthreads();          // protect smem from previous MMA reads

        // ---- A planes: cp.async copies (2048 16B chunks per plane)
#pragma unroll
        for (int it = 0; it < 8; it++) {
            int idx = tid + it * 256;
            int row = idx >> 4;
            int c8 = (idx & 15) * 8;
            cpa16(sAH + (row * PA1 + c8) * 2, &g_xh[(m0 + row) * KI + kb + c8]);
            cpa16(sAL + (row * PA1 + c8) * 2, &g_xl[(m0 + row) * KI + kb + c8]);
        }
        // ---- B planes: cp.async copies (2560 16B chunks per plane)
#pragma unroll
        for (int it = 0; it < 10; it++) {
            int idx = tid + it * 256;
            int ju = idx >> 4;
            int c8 = (idx & 15) * 8;
            cpa16(sBH + (ju * PA1 + c8) * 2, &g_Wbh[ju * KI + kb + c8]);
            cpa16(sBL + (ju * PA1 + c8) * 2, &g_Wbl[ju * KI + kb + c8]);
        }
        CP_WAIT_ALL();
        __syncthreads();

#pragma unroll
        for (int ph = 0; ph < 3; ph++) {
            const uint32_t aBase = aPl[ph];
            const uint32_t bBase = bPl[ph];
#pragma unroll
            for (int ks8 = 0; ks8 < 8; ks8++) {
                const int k0 = ks8 * 16;
                uint32_t a0[4], a1[4];
                ldm_x4(a0, aBase + k0 * 2);
                ldm_x4(a1, aBase + (16 * PA1 + k0) * 2);
#pragma unroll
                for (int p = 0; p < 5; p++) {
                    uint32_t b[4];
                    ldm_x4(b, bBase + (16 * p * PA1 + k0) * 2);
                    mma16816(acc[0][2 * p], a0, b);
                    mma16816(acc[0][2 * p + 1], a0, b + 2);
                    mma16816(acc[1][2 * p], a1, b);
                    mma16816(acc[1][2 * p + 1], a1, b + 2);
                }
            }
        }
    }

    float* out = &g_spart[ky * (BB * JU)];
    const int mrow = m0 + m_off + (lane >> 2);
    const int ncol = n_off + 2 * (lane & 3);
#pragma unroll
    for (int mf = 0; mf < 2; mf++)
#pragma unroll
        for (int nf = 0; nf < 10; nf++) {
            const float* d = acc[mf][nf];
            int m = mrow + 16 * mf;
            int n = ncol + 8 * nf;
            *reinterpret_cast<float2*>(&out[m * JU + n]) = make_float2(d[0], d[1]);
            *reinterpret_cast<float2*>(&out[(m + 8) * JU + n]) = make_float2(d[2], d[3]);
        }
}

// ===========================================================================
// GEMM2 (mma.sync + ldmatrix.trans, cp.async pure-copy prologue):
//   Gpart[by][ki][ju] = x^T[ki, 256-bchunk] @ v[bchunk, ju]
__global__ __launch_bounds__(256, 1) void gemm2mma_k() {
    extern __shared__ char smem[];
    __nv_bfloat16* AH = reinterpret_cast<__nv_bfloat16*>(smem + G2_AH);
    __nv_bfloat16* AL = reinterpret_cast<__nv_bfloat16*>(smem + G2_AL);
    __nv_bfloat16* BH = reinterpret_cast<__nv_bfloat16*>(smem + G2_BH);
    __nv_bfloat16* BL = reinterpret_cast<__nv_bfloat16*>(smem + G2_BL);
    const int tid = threadIdx.x;
    const int m0 = blockIdx.x * 128;            // over KI

    const int lane = tid & 31;
    const int wid = tid >> 5;
    const int m_off = (wid & 3) * 32;
    const int n_off = (wid >> 2) * 80;

    const uint32_t aOff = (((lane & 7) + ((lane >> 4) << 3)) * PA2
                           + m_off + ((lane >> 3) & 1) * 8) * 2;
    const uint32_t bOff = (((lane & 7) + ((lane >> 3) & 1) * 8) * PB2
                           + n_off + ((lane >> 4) << 3)) * 2;
    uint32_t aPl[3] = {s2u(AH) + aOff, s2u(AH) + aOff, s2u(AL) + aOff};
    uint32_t bPl[3] = {s2u(BH) + bOff, s2u(BL) + bOff, s2u(BH) + bOff};

    const uint32_t sAH = s2u(AH), sAL = s2u(AL), sBH = s2u(BH), sBL = s2u(BL);

    float acc[2][10][4];
#pragma unroll
    for (int mf = 0; mf < 2; mf++)
#pragma unroll
        for (int nf = 0; nf < 10; nf++)
#pragma unroll
            for (int q = 0; q < 4; q++) acc[mf][nf][q] = 0.0f;

#pragma unroll
    for (int half = 0; half < 2; half++) {
        const int kb0 = blockIdx.y * BCHUNK + half * 128;
        if (half) __syncthreads();

        // ---- A planes: x rows (2048 16B chunks per plane)
#pragma unroll
        for (int it = 0; it < 8; it++) {
            int idx = tid + it * 256;
            int bb = idx >> 4;
            int m8 = (idx & 15) * 8;
            cpa16(sAH + (bb * PA2 + m8) * 2, &g_xh[(kb0 + bb) * KI + m0 + m8]);
            cpa16(sAL + (bb * PA2 + m8) * 2, &g_xl[(kb0 + bb) * KI + m0 + m8]);
        }
        // ---- B planes: v rows (2560 16B chunks per plane; 20 per row)
#pragma unroll
        for (int it = 0; it < 10; it++) {
            int idx = tid + it * 256;
            int bb = idx / 20;
            int j8 = (idx - bb * 20) * 8;
            cpa16(sBH + (bb * PB2 + j8) * 2, &g_vh[(kb0 + bb) * JU + j8]);
            cpa16(sBL + (bb * PB2 + j8) * 2, &g_vl[(kb0 + bb) * JU + j8]);
        }
        CP_WAIT_ALL();
        __syncthreads();

#pragma unroll
        for (int ph = 0; ph < 3; ph++) {
            const uint32_t aBase = aPl[ph];
            const uint32_t bBase = bPl[ph];
#pragma unroll
            for (int ks8 = 0; ks8 < 8; ks8++) {
                const int k0 = ks8 * 16;
                uint32_t a0[4], a1[4];
                ldm_x4t(a0, aBase + k0 * PA2 * 2);
                ldm_x4t(a1, aBase + (k0 * PA2 + 16) * 2);
#pragma unroll
                for (int p = 0; p < 5; p++) {
                    uint32_t b[4];
                    ldm_x4t(b, bBase + (k0 * PB2 + 16 * p) * 2);
                    mma16816(acc[0][2 * p], a0, b);
                    mma16816(acc[0][2 * p + 1], a0, b + 2);
                    mma16816(acc[1][2 * p], a1, b);
                    mma16816(acc[1][2 * p + 1], a1, b + 2);
                }
            }
        }
    }

    float* out = g_Gpart[blockIdx.y];
    const int mrow = m0 + m_off + (lane >> 2);
    const int ncol = n_off + 2 * (lane & 3);
#pragma unroll
    for (int mf = 0; mf < 2; mf++)
#pragma unroll
        for (int nf = 0; nf < 10; nf++) {
            const float* d = acc[mf][nf];
            int m = mrow + 16 * mf;
            int n = ncol + 8 * nf;
            *reinterpret_cast<float2*>(&out[m * JU + n]) = make_float2(d[0], d[1]);
            *reinterpret_cast<float2*>(&out[(m + 8) * JU + n]) = make_float2(d[2], d[3]);
        }
}

// ===========================================================================
// fused reduceS + squash: block per b; emits v bf16 hi/lo planes (or final out)
__global__ __launch_bounds__(160) void squashred_k(float* __restrict__ out, int writeOut) {
    __shared__ float sj[JU];
    __shared__ float scl[US];
    const int b = blockIdx.x;
    const int ju = threadIdx.x;
    float acc = 0.0f;
#pragma unroll 6
    for (int ks = 0; ks < KSPLIT; ks++)
        acc += g_spart[ks * (BB * JU) + b * JU + ju];
    sj[ju] = acc;
    __syncthreads();
    if (ju < US) {
        float msq = 0.0f;
#pragma unroll
        for (int j = 0; j < NU; j++) {
            float v = sj[j * US + ju];
            msq += v * v;
        }
        float mag = sqrtf(msq);
        scl[ju] = msq / ((BETA + msq) * mag);
    }
    __syncthreads();
    float r = sj[ju] * scl[ju & 15];
    if (writeOut) {
        out[b * JU + ju] = r;
    } else {
        __nv_bfloat16 h, l;
        split_bf16(r, h, l);
        g_vh[b * JU + ju] = h;
        g_vl[b * JU + ju] = l;
    }
}

// b_T[j][i] = (1/B) * sum_{k,u} Wt * (ΣGpart)
__global__ void bupdate_k() {
    int gw = (blockIdx.x * blockDim.x + threadIdx.x) >> 5;
    int lane = threadIdx.x & 31;
    if (gw >= INCH * NU) return;
    int i = gw / NU;
    int j = gw - i * NU;
    int k = lane >> 2;
    int u = (lane & 3) * 4;
    int idx = (k * INCH + i) * JU + j * US + u;
    float4 w = *reinterpret_cast<const float4*>(&g_Wt[idx]);
    float4 g = *reinterpret_cast<const float4*>(&g_Gpart[0][idx]);
#pragma unroll
    for (int s = 1; s < BSPLIT; s++) {
        float4 gs = *reinterpret_cast<const float4*>(&g_Gpart[s][idx]);
        g.x += gs.x; g.y += gs.y; g.z += gs.z; g.w += gs.w;
    }
    float acc = w.x * g.x + w.y * g.y + w.z * g.z + w.w * g.w;
#pragma unroll
    for (int o = 16; o > 0; o >>= 1) acc += __shfl_xor_sync(0xffffffffu, acc, o);
    if (lane == 0) g_bT[j * INCH + i] = acc * (1.0f / (float)BB);
}

// ---------------------------------------------------------------------------
extern "C" void kernel_launch(void* const* d_in, const int* in_sizes, int n_in,
                              void* d_out, int out_size) {
    const float* x = (const float*)d_in[0];
    const float* W = (const float*)d_in[1];
    if (n_in >= 2 && in_sizes[0] == INCH * NU * US * INU) {
        const float* t = x; x = W; W = t;
    }
    float* out = (float*)d_out;

    cudaFuncSetAttribute(gemm1mma_k, cudaFuncAttributeMaxDynamicSharedMemorySize, SMEM_G1);
    cudaFuncSetAttribute(gemm2mma_k, cudaFuncAttributeMaxDynamicSharedMemorySize, SMEM_G2);

    // launches: 0 transposeW, 1 transposeW2, 2 splitX, 3 pad, 4 scaleWb,
    // 5 gemm1mma (ncu -s 5 -c 1 capture target)
    transposeW_k<<<(INCH * JU + 255) / 256, 256>>>(W);
    transposeW2_k<<<dim3(KI / 32, JU / 32), dim3(32, 8)>>>();
    splitX_k<<<(BB * KI / 4 + 255) / 256, 256>>>(x);
    pad_k<<<1, 32>>>();

    for (int t = 0; t < 3; t++) {
        if (t > 0) softmax_k<<<NU, 128>>>();
        scaleWb_k<<<(JU * KI / 4 + 255) / 256, 256>>>(t == 0 ? 1 : 0);
        gemm1mma_k<<<dim3(BB / 128, KSPLIT), 256, SMEM_G1>>>();
        squashred_k<<<BB, 160>>>(out, t == 2 ? 1 : 0);
        if (t < 2) {
            gemm2mma_k<<<dim3(KI / 128, BSPLIT), 256, SMEM_G2>>>();
            bupdate_k<<<(INCH * NU * 32) / 256, 256>>>();
        }
    }
}